// round 4
// baseline (speedup 1.0000x reference)
#include <cuda_runtime.h>
#include <cstdint>
#include <cstddef>

// Jordan GRU, B=128, T=2048, I=128, H=256, O=64.
// 16 clusters of 8 CTAs (one cluster per batch-group of 8 rows; CTA = hidden
// slice of 32 units). Per-step h (1KB/slice) and y (256B/slice) exchanged via
// st.async DSMEM pushes + transaction mbarriers. 512 threads, split-K.

#define TSTEPS 2048
#define INSZ 128
#define HID 256
#define OUTSZ 64
#define GIN 192
#define NBLK 128
#define NTHR 512
#define ROWS 8
#define UNITS 32

#define HS 260
#define XS 132
#define YS 68
#define WHS 264
#define WIS 200
#define FCS 264

// float-offsets inside dynamic smem
#define OFF_MB   0                           // 4 mbarriers (8 floats)
#define OFF_H    8                           // 2 * 8 * 260
#define OFF_X    (OFF_H + 2 * ROWS * HS)     // 4168
#define OFF_Y    (OFF_X + ROWS * XS)         // 5224
#define OFF_P    (OFF_Y + ROWS * YS)         // 5768 (256 float4)
#define OFF_WHH  (OFF_P + 1024)              // 6792
#define OFF_WIH  (OFF_WHH + 96 * WHS)        // 32136
#define OFF_FC   (OFF_WIH + 96 * WIS)        // 51336
#define OFF_BIH  (OFF_FC + 8 * FCS)          // 53448
#define OFF_BHH  (OFF_BIH + 96)
#define OFF_FCB  (OFF_BHH + 96)
#define SMEM_FLOATS (OFF_FCB + 8)            // 53648 -> 214592 B

#define HBYTES (ROWS * UNITS * 4 * 8)        // 8192 expected h bytes/step
#define YBYTES (ROWS * 8 * 4 * 8)            // 2048 expected y bytes/step

typedef unsigned long long ull;

__device__ __forceinline__ ull ffma2(ull a, ull b, ull c) {
    ull d; asm("fma.rn.f32x2 %0, %1, %2, %3;" : "=l"(d) : "l"(a), "l"(b), "l"(c));
    return d;
}
__device__ __forceinline__ ull packf2(float lo, float hi) {
    ull r; asm("mov.b64 %0, {%1, %2};" : "=l"(r) : "f"(lo), "f"(hi));
    return r;
}
__device__ __forceinline__ float sumf2(ull v) {
    float a, b; asm("mov.b64 {%0, %1}, %2;" : "=f"(a), "=f"(b) : "l"(v));
    return a + b;
}
__device__ __forceinline__ uint32_t smem_u32(const void* p) {
    uint32_t a;
    asm("{ .reg .u64 t; cvta.to.shared.u64 t, %1; cvt.u32.u64 %0, t; }"
        : "=r"(a) : "l"(p));
    return a;
}
__device__ __forceinline__ uint32_t mapa32(uint32_t a, uint32_t rank) {
    uint32_t d; asm("mapa.shared::cluster.u32 %0, %1, %2;" : "=r"(d) : "r"(a), "r"(rank));
    return d;
}
__device__ __forceinline__ void mbar_init(uint32_t mb, uint32_t cnt) {
    asm volatile("mbarrier.init.shared.b64 [%0], %1;" :: "r"(mb), "r"(cnt) : "memory");
}
__device__ __forceinline__ void mbar_expect(uint32_t mb, uint32_t tx) {
    asm volatile("mbarrier.arrive.expect_tx.shared.b64 _, [%0], %1;"
                 :: "r"(mb), "r"(tx) : "memory");
}
__device__ __forceinline__ void st_async64(uint32_t raddr, ull v, uint32_t rmbar) {
    asm volatile("st.async.shared::cluster.mbarrier::complete_tx::bytes.b64 [%0], %1, [%2];"
                 :: "r"(raddr), "l"(v), "r"(rmbar) : "memory");
}
__device__ __forceinline__ void wait_parity(uint32_t mb, uint32_t ph) {
    uint32_t done;
    asm volatile(
        "{\n\t.reg .pred p;\n\t"
        "mbarrier.try_wait.parity.acquire.cluster.shared::cta.b64 p, [%1], %2, 0x989680;\n\t"
        "selp.b32 %0, 1, 0, p;\n\t}"
        : "=r"(done) : "r"(mb), "r"(ph) : "memory");
    while (!done) {
        asm volatile(
            "{\n\t.reg .pred p;\n\t"
            "mbarrier.try_wait.parity.acquire.cluster.shared::cta.b64 p, [%1], %2, 0x989680;\n\t"
            "selp.b32 %0, 1, 0, p;\n\t}"
            : "=r"(done) : "r"(mb), "r"(ph) : "memory");
    }
}
__device__ __forceinline__ void cluster_sync_all() {
    asm volatile("barrier.cluster.arrive.aligned;" ::: "memory");
    asm volatile("barrier.cluster.wait.aligned;" ::: "memory");
}

__global__ void __launch_bounds__(NTHR, 1) __cluster_dims__(8, 1, 1)
jordan_kernel(
    const float* __restrict__ x,      // [B, T, I]
    const float* __restrict__ w_ih,   // [3H, GIN]
    const float* __restrict__ w_hh,   // [3H, H]
    const float* __restrict__ b_ih,   // [3H]
    const float* __restrict__ b_hh,   // [3H]
    const float* __restrict__ fc_w,   // [O, H]
    const float* __restrict__ fc_b,   // [O]
    float* __restrict__ out)          // [B, O]
{
    extern __shared__ float sm[];
    const uint32_t sbase = smem_u32(sm);

    float* h_s   = sm + OFF_H;     // [2][8][HS]
    float* x_s   = sm + OFF_X;     // [8][XS]
    float* y_s   = sm + OFF_Y;     // [8][YS]
    float4* p_s  = reinterpret_cast<float4*>(sm + OFF_P);   // [256]
    float* whh_s = sm + OFF_WHH;   // [96][WHS]
    float* wih_s = sm + OFF_WIH;   // [96][WIS]
    float* fc_s  = sm + OFF_FC;    // [8][FCS]
    float* bih_s = sm + OFF_BIH;
    float* bhh_s = sm + OFF_BHH;
    float* fcb_s = sm + OFF_FCB;

    const uint32_t hbar[2] = { sbase + OFF_MB * 4,      sbase + OFF_MB * 4 + 8 };
    const uint32_t ybar[2] = { sbase + OFF_MB * 4 + 16, sbase + OFF_MB * 4 + 24 };

    const int tid  = threadIdx.x;
    const int lane = tid & 31;
    const int warp = tid >> 5;
    const int half = warp >> 3;                 // K-half
    const int b    = lane & 7;                  // local batch row
    const int unit = (warp & 7) * 4 + (lane >> 3);

    const int blk   = blockIdx.x;
    const int slice = blk & 7;                  // cluster rank
    const int b0    = (blk >> 3) * ROWS;        // first global batch row

    // ---- init smem: weights, biases, state, barriers ----
    for (int i = tid; i < 96 * HID; i += NTHR) {
        int row = i >> 8, k = i & 255;
        whh_s[row * WHS + k] = w_hh[((row >> 5) * HID + slice * UNITS + (row & 31)) * HID + k];
    }
    for (int i = tid; i < 96 * GIN; i += NTHR) {
        int row = i / GIN, k = i - row * GIN;
        wih_s[row * WIS + k] = w_ih[((row >> 5) * HID + slice * UNITS + (row & 31)) * GIN + k];
    }
    for (int i = tid; i < 8 * HID; i += NTHR) {
        int r = i >> 8, k = i & 255;
        fc_s[r * FCS + k] = fc_w[(slice * 8 + r) * HID + k];
    }
    if (tid < 96) {
        int grow = (tid >> 5) * HID + slice * UNITS + (tid & 31);
        bih_s[tid] = b_ih[grow];
        bhh_s[tid] = b_hh[grow];
    }
    if (tid < 8) fcb_s[tid] = fc_b[slice * 8 + tid];
    for (int i = tid; i < ROWS * HS; i += NTHR) h_s[i] = 0.0f;      // buf 0
    for (int i = tid; i < ROWS * YS; i += NTHR) y_s[i] = 0.0f;
    if (tid == 0) {
        mbar_init(hbar[0], 1); mbar_init(hbar[1], 1);
        mbar_init(ybar[0], 1); mbar_init(ybar[1], 1);
    }
    __syncthreads();
    cluster_sync_all();

    // peer smem window bases
    uint32_t peer[8];
    #pragma unroll
    for (int j = 0; j < 8; j++) peer[j] = mapa32(sbase, (uint32_t)j);

    // per-use phase parity counters
    uint32_t hph0 = 0, hph1 = 0, yph0 = 0, yph1 = 0;

    const float* wiR = wih_s + (0 * UNITS + unit) * WIS;
    const float* wiZ = wih_s + (1 * UNITS + unit) * WIS;
    const float* wiN = wih_s + (2 * UNITS + unit) * WIS;
    const float* whR = whh_s + (0 * UNITS + unit) * WHS;
    const float* whZ = whh_s + (1 * UNITS + unit) * WHS;
    const float* whN = whh_s + (2 * UNITS + unit) * WHS;

    for (int t = 0; t < TSTEPS; t++) {
        const int cur = t & 1, nxt = cur ^ 1;
        float* hbuf = h_s + cur * ROWS * HS;

        // stage x_t (coalesced; independent of recurrence)
        if (tid < 256) {
            int row = tid >> 5, c = tid & 31;
            float4 v = reinterpret_cast<const float4*>(x)
                           [((size_t)(b0 + row) * TSTEPS + t) * 32 + c];
            *reinterpret_cast<float4*>(x_s + row * XS + c * 4) = v;
        }

        if (t > 0) {
            if (tid == 0) {
                mbar_expect(hbar[cur], HBYTES);
                mbar_expect(ybar[cur], YBYTES);
            }
            uint32_t ph = cur ? hph1 : hph0;
            wait_parity(hbar[cur], ph);
            if (cur) hph1 ^= 1; else hph0 ^= 1;
        }
        __syncthreads();

        // y_t = tanh(fc(h_t)) piece: warps 0-1, this slice's 8 fc rows
        if (t > 0 && tid < 64) {
            const int yb = tid & 7, ol = (tid >> 3) & 7;
            const ulonglong2* hp = reinterpret_cast<const ulonglong2*>(hbuf + yb * HS);
            const ulonglong2* fp = reinterpret_cast<const ulonglong2*>(fc_s + ol * FCS);
            ull a0 = 0, a1 = 0;
            #pragma unroll 8
            for (int c = 0; c < 64; c++) {
                ulonglong2 hv = hp[c], fv = fp[c];
                a0 = ffma2(hv.x, fv.x, a0);
                a1 = ffma2(hv.y, fv.y, a1);
            }
            float yv = tanhf(sumf2(a0) + sumf2(a1) + fcb_s[ol]);
            float yp = __shfl_xor_sync(0xffffffffu, yv, 8);
            if (((tid >> 3) & 1) == 0) {           // even ol packs (ol, ol+1)
                ull pv = packf2(yv, yp);
                uint32_t off = (uint32_t)(OFF_Y + yb * YS + slice * 8 + ol) * 4u;
                uint32_t mboff = cur ? (OFF_MB * 4 + 24) : (OFF_MB * 4 + 16);
                #pragma unroll
                for (int j = 0; j < 8; j++)
                    st_async64(peer[j] + off, pv, peer[j] + mboff);
            }
        }

        // accumulators (this thread's K-half)
        ull aRe = 0, aRo = 0, aZe = 0, aZo = 0;
        ull aNie = 0, aNio = 0, aNhe = 0, aNho = 0;

        // gh = h_t @ w_hh^T  (K-half: 128 values)
        {
            const ulonglong2* hp = reinterpret_cast<const ulonglong2*>(hbuf + b * HS + half * 128);
            const ulonglong2* r0 = reinterpret_cast<const ulonglong2*>(whR + half * 128);
            const ulonglong2* r1 = reinterpret_cast<const ulonglong2*>(whZ + half * 128);
            const ulonglong2* r2 = reinterpret_cast<const ulonglong2*>(whN + half * 128);
            #pragma unroll 8
            for (int c = 0; c < 32; c++) {
                ulonglong2 hv = hp[c];
                ulonglong2 v0 = r0[c];
                aRe = ffma2(hv.x, v0.x, aRe); aRo = ffma2(hv.y, v0.y, aRo);
                ulonglong2 v1 = r1[c];
                aZe = ffma2(hv.x, v1.x, aZe); aZo = ffma2(hv.y, v1.y, aZo);
                ulonglong2 v2 = r2[c];
                aNhe = ffma2(hv.x, v2.x, aNhe); aNho = ffma2(hv.y, v2.y, aNho);
            }
        }
        // gi_x  (K-half: 64 values)
        {
            const ulonglong2* xp = reinterpret_cast<const ulonglong2*>(x_s + b * XS + half * 64);
            const ulonglong2* r0 = reinterpret_cast<const ulonglong2*>(wiR + half * 64);
            const ulonglong2* r1 = reinterpret_cast<const ulonglong2*>(wiZ + half * 64);
            const ulonglong2* r2 = reinterpret_cast<const ulonglong2*>(wiN + half * 64);
            #pragma unroll 8
            for (int c = 0; c < 16; c++) {
                ulonglong2 xv = xp[c];
                ulonglong2 v0 = r0[c];
                aRe = ffma2(xv.x, v0.x, aRe); aRo = ffma2(xv.y, v0.y, aRo);
                ulonglong2 v1 = r1[c];
                aZe = ffma2(xv.x, v1.x, aZe); aZo = ffma2(xv.y, v1.y, aZo);
                ulonglong2 v2 = r2[c];
                aNie = ffma2(xv.x, v2.x, aNie); aNio = ffma2(xv.y, v2.y, aNio);
            }
        }

        // wait for all y pieces (normally already complete), then gi_y
        if (t > 0) {
            uint32_t ph = cur ? yph1 : yph0;
            wait_parity(ybar[cur], ph);
            if (cur) yph1 ^= 1; else yph0 ^= 1;
        }
        {
            const ulonglong2* yp = reinterpret_cast<const ulonglong2*>(y_s + b * YS + half * 32);
            const ulonglong2* r0 = reinterpret_cast<const ulonglong2*>(wiR + INSZ + half * 32);
            const ulonglong2* r1 = reinterpret_cast<const ulonglong2*>(wiZ + INSZ + half * 32);
            const ulonglong2* r2 = reinterpret_cast<const ulonglong2*>(wiN + INSZ + half * 32);
            #pragma unroll
            for (int c = 0; c < 8; c++) {
                ulonglong2 yv = yp[c];
                ulonglong2 v0 = r0[c];
                aRe = ffma2(yv.x, v0.x, aRe); aRo = ffma2(yv.y, v0.y, aRo);
                ulonglong2 v1 = r1[c];
                aZe = ffma2(yv.x, v1.x, aZe); aZo = ffma2(yv.y, v1.y, aZo);
                ulonglong2 v2 = r2[c];
                aNie = ffma2(yv.x, v2.x, aNie); aNio = ffma2(yv.y, v2.y, aNio);
            }
        }

        float pR  = sumf2(aRe)  + sumf2(aRo);
        float pZ  = sumf2(aZe)  + sumf2(aZo);
        float pNi = sumf2(aNie) + sumf2(aNio);
        float pNh = sumf2(aNhe) + sumf2(aNho);

        if (half == 1) p_s[(warp & 7) * 32 + lane] = make_float4(pR, pZ, pNi, pNh);
        __syncthreads();

        if (half == 0) {
            float4 pp = p_s[warp * 32 + lane];
            float preR = pR + pp.x + bih_s[unit]      + bhh_s[unit];
            float preZ = pZ + pp.y + bih_s[32 + unit] + bhh_s[32 + unit];
            float giN  = pNi + pp.z + bih_s[64 + unit];
            float ghN  = pNh + pp.w + bhh_s[64 + unit];
            float r = 1.0f / (1.0f + __expf(-preR));
            float z = 1.0f / (1.0f + __expf(-preZ));
            float n = tanhf(giN + r * ghN);
            float hprev = hbuf[b * HS + slice * UNITS + unit];
            float hnew = (1.0f - z) * n + z * hprev;

            // broadcast h_{t+1}: pack (even,odd) unit pair, push to all 8 CTAs
            float hp2 = __shfl_xor_sync(0xffffffffu, hnew, 8);
            if (((lane >> 3) & 1) == 0) {          // even unit lanes
                ull pv = packf2(hnew, hp2);
                uint32_t off = (uint32_t)(OFF_H + (nxt * ROWS + b) * HS +
                                          slice * UNITS + unit) * 4u;
                uint32_t mboff = nxt ? (OFF_MB * 4 + 8) : (OFF_MB * 4);
                #pragma unroll
                for (int j = 0; j < 8; j++)
                    st_async64(peer[j] + off, pv, peer[j] + mboff);
            }
        }
    }

    // final: wait h_T (buffer 0), y_T = tanh(fc(h_T)) -> out
    if (tid == 0) mbar_expect(hbar[0], HBYTES);
    wait_parity(hbar[0], hph0);
    __syncthreads();
    if (tid < 64) {
        const int yb = tid & 7, ol = (tid >> 3) & 7;
        const ulonglong2* hp = reinterpret_cast<const ulonglong2*>(h_s + yb * HS);
        const ulonglong2* fp = reinterpret_cast<const ulonglong2*>(fc_s + ol * FCS);
        ull a0 = 0, a1 = 0;
        #pragma unroll 8
        for (int c = 0; c < 64; c++) {
            ulonglong2 hv = hp[c], fv = fp[c];
            a0 = ffma2(hv.x, fv.x, a0);
            a1 = ffma2(hv.y, fv.y, a1);
        }
        out[(b0 + yb) * OUTSZ + slice * 8 + ol] =
            tanhf(sumf2(a0) + sumf2(a1) + fcb_s[ol]);
    }
    cluster_sync_all();
}

extern "C" void kernel_launch(void* const* d_in, const int* in_sizes, int n_in,
                              void* d_out, int out_size) {
    (void)in_sizes; (void)n_in; (void)out_size;
    const float* x    = (const float*)d_in[0];
    const float* w_ih = (const float*)d_in[1];
    const float* w_hh = (const float*)d_in[2];
    const float* b_ih = (const float*)d_in[3];
    const float* b_hh = (const float*)d_in[4];
    const float* fc_w = (const float*)d_in[5];
    const float* fc_b = (const float*)d_in[6];
    float* out = (float*)d_out;

    const int smem_bytes = SMEM_FLOATS * (int)sizeof(float); // 214,592 B
    cudaFuncSetAttribute(jordan_kernel,
                         cudaFuncAttributeMaxDynamicSharedMemorySize,
                         smem_bytes);

    jordan_kernel<<<NBLK, NTHR, smem_bytes>>>(x, w_ih, w_hh, b_ih, b_hh,
                                              fc_w, fc_b, out);
}

// round 5
// speedup vs baseline: 1.6373x; 1.6373x over previous
#include <cuda_runtime.h>
#include <cstdint>
#include <cstddef>

// Jordan GRU, B=128, T=2048, I=128, H=256, O=64.
// 16 groups x 8 slices; block = 8 batch rows x 32 hidden units, 512 threads,
// split-K (2 halves). Group-local L2 exchange of h/y with release/acquire
// flags. y computed by warps 0-1 (non-blocking for others), x double-buffered.

#define TSTEPS 2048
#define INSZ 128
#define HID 256
#define OUTSZ 64
#define GIN 192
#define NBLK 128
#define NTHR 512
#define ROWS 8
#define UNITS 32
#define NSLICE 8

#define HS 260
#define XS 132
#define YS 68
#define WHS 264
#define WIS 200
#define FCS 264
#define HSTG 36

typedef unsigned long long ull;

__device__ float g_h[2][128 * HID];
__device__ float g_y[2][128 * OUTSZ];
__device__ unsigned g_hflag[NBLK];
__device__ unsigned g_yflag[NBLK];

__device__ __forceinline__ ull ffma2(ull a, ull b, ull c) {
    ull d; asm("fma.rn.f32x2 %0, %1, %2, %3;" : "=l"(d) : "l"(a), "l"(b), "l"(c));
    return d;
}
__device__ __forceinline__ float sumf2(ull v) {
    float a, b; asm("mov.b64 {%0, %1}, %2;" : "=f"(a), "=f"(b) : "l"(v));
    return a + b;
}
__device__ __forceinline__ unsigned ld_acq(const unsigned* p) {
    unsigned v; asm volatile("ld.acquire.gpu.global.u32 %0, [%1];" : "=r"(v) : "l"(p));
    return v;
}
__device__ __forceinline__ void st_rel(unsigned* p, unsigned v) {
    asm volatile("st.release.gpu.global.u32 [%0], %1;" :: "l"(p), "r"(v));
}
__device__ __forceinline__ void barn(int id, int cnt) {
    asm volatile("bar.sync %0, %1;" :: "r"(id), "r"(cnt) : "memory");
}

__global__ void jordan_init_kernel() {
    const int stride = gridDim.x * blockDim.x;
    const int n = 128 * HID + 128 * OUTSZ + 2 * NBLK;
    for (int i = blockIdx.x * blockDim.x + threadIdx.x; i < n; i += stride) {
        if (i < 128 * HID) g_h[0][i] = 0.0f;
        else if (i < 128 * HID + 128 * OUTSZ) g_y[0][i - 128 * HID] = 0.0f;
        else {
            int f = i - 128 * HID - 128 * OUTSZ;
            if (f < NBLK) g_hflag[f] = 0u; else g_yflag[f - NBLK] = 0u;
        }
    }
}

__global__ void __launch_bounds__(NTHR, 1) jordan_kernel(
    const float* __restrict__ x,      // [B, T, I]
    const float* __restrict__ w_ih,   // [3H, GIN]
    const float* __restrict__ w_hh,   // [3H, H]
    const float* __restrict__ b_ih,   // [3H]
    const float* __restrict__ b_hh,   // [3H]
    const float* __restrict__ fc_w,   // [O, H]
    const float* __restrict__ fc_b,   // [O]
    float* __restrict__ out)          // [B, O]
{
    extern __shared__ float sm[];
    float*  h_s    = sm;                         // 8*260
    float*  x_s    = h_s + ROWS * HS;            // 8*132
    float*  y_s    = x_s + ROWS * XS;            // 8*68
    float4* p_s    = reinterpret_cast<float4*>(y_s + ROWS * YS); // 256
    float*  hstg_s = reinterpret_cast<float*>(p_s + 256);        // 8*36
    float*  whh_s  = hstg_s + ROWS * HSTG;       // 96*264
    float*  wih_s  = whh_s + 96 * WHS;           // 96*200
    float*  fc_s   = wih_s + 96 * WIS;           // 8*264
    float*  bih_s  = fc_s + 8 * FCS;             // 96
    float*  bhh_s  = bih_s + 96;                 // 96
    float*  fcb_s  = bhh_s + 96;                 // 8

    const int tid  = threadIdx.x;
    const int lane = tid & 31;
    const int warp = tid >> 5;
    const int half = warp >> 3;
    const int b    = lane & 7;
    const int unit = (warp & 7) * 4 + (lane >> 3);

    const int blk   = blockIdx.x;
    const int group = blk >> 3;
    const int slice = blk & 7;
    const int b0    = group * ROWS;
    const int fbase = group * NSLICE;

    // ---- weights/biases into smem ----
    for (int i = tid; i < 96 * HID; i += NTHR) {
        int row = i >> 8, k = i & 255;
        whh_s[row * WHS + k] = w_hh[((row >> 5) * HID + slice * UNITS + (row & 31)) * HID + k];
    }
    for (int i = tid; i < 96 * GIN; i += NTHR) {
        int row = i / GIN, k = i - row * GIN;
        wih_s[row * WIS + k] = w_ih[((row >> 5) * HID + slice * UNITS + (row & 31)) * GIN + k];
    }
    for (int i = tid; i < 8 * HID; i += NTHR) {
        int r = i >> 8, k = i & 255;
        fc_s[r * FCS + k] = fc_w[(slice * 8 + r) * HID + k];
    }
    if (tid < 96) {
        int grow = (tid >> 5) * HID + slice * UNITS + (tid & 31);
        bih_s[tid] = b_ih[grow];
        bhh_s[tid] = b_hh[grow];
    }
    if (tid < 8) fcb_s[tid] = fc_b[slice * 8 + tid];
    for (int i = tid; i < ROWS * YS; i += NTHR) y_s[i] = 0.0f;
    __syncthreads();

    const float* wiR = wih_s + (0 * UNITS + unit) * WIS;
    const float* wiZ = wih_s + (1 * UNITS + unit) * WIS;
    const float* wiN = wih_s + (2 * UNITS + unit) * WIS;
    const float* whR = whh_s + (0 * UNITS + unit) * WHS;
    const float* whZ = whh_s + (1 * UNITS + unit) * WHS;
    const float* whN = whh_s + (2 * UNITS + unit) * WHS;

    // x prefetch for t=0
    float4 xreg;
    if (tid < 256) {
        int row = tid >> 5, c = tid & 31;
        xreg = reinterpret_cast<const float4*>(x)[((size_t)(b0 + row) * TSTEPS) * 32 + c];
    }

    for (int t = 0; t < TSTEPS; t++) {
        const int cur = t & 1, nxt = cur ^ 1;

        // store prefetched x_t; start LDG for x_{t+1}
        if (tid < 256) {
            int row = tid >> 5, c = tid & 31;
            *reinterpret_cast<float4*>(x_s + row * XS + c * 4) = xreg;
            if (t + 1 < TSTEPS)
                xreg = reinterpret_cast<const float4*>(x)
                           [((size_t)(b0 + row) * TSTEPS + t + 1) * 32 + c];
        }

        // wait for h_t flags, then stage h_t (one float4 per thread)
        if (tid < NSLICE) { while ((int)ld_acq(&g_hflag[fbase + tid]) < t) { } }
        __syncthreads();                                   // S1
        {
            int row = tid >> 6, c = tid & 63;
            float4 v = reinterpret_cast<const float4*>(g_h[cur])[(b0 + row) * 64 + c];
            *reinterpret_cast<float4*>(h_s + row * HS + c * 4) = v;
        }
        __syncthreads();                                   // S2

        // y_t piece (warps 0-1 only; others proceed to gh)
        if (t > 0) {
            if (tid < 64) {
                const int yb = tid & 7, ol = tid >> 3;
                const ulonglong2* hp = reinterpret_cast<const ulonglong2*>(h_s + yb * HS);
                const ulonglong2* fp = reinterpret_cast<const ulonglong2*>(fc_s + ol * FCS);
                ull a0 = 0, a1 = 0;
                #pragma unroll 8
                for (int c = 0; c < 64; c++) {
                    ulonglong2 hv = hp[c], fv = fp[c];
                    a0 = ffma2(hv.x, fv.x, a0);
                    a1 = ffma2(hv.y, fv.y, a1);
                }
                g_y[cur][(b0 + yb) * OUTSZ + slice * 8 + ol] =
                    tanhf(sumf2(a0) + sumf2(a1) + fcb_s[ol]);
                __threadfence();
                barn(1, 64);
                if (tid == 0) st_rel(&g_yflag[blk], (unsigned)t);
            }
        }

        ull aRe = 0, aRo = 0, aZe = 0, aZo = 0;
        ull aNie = 0, aNio = 0, aNhe = 0, aNho = 0;

        // gh (K-half of 256)
        {
            const ulonglong2* hp = reinterpret_cast<const ulonglong2*>(h_s + b * HS + half * 128);
            const ulonglong2* r0 = reinterpret_cast<const ulonglong2*>(whR + half * 128);
            const ulonglong2* r1 = reinterpret_cast<const ulonglong2*>(whZ + half * 128);
            const ulonglong2* r2 = reinterpret_cast<const ulonglong2*>(whN + half * 128);
            #pragma unroll 8
            for (int c = 0; c < 32; c++) {
                ulonglong2 hv = hp[c];
                ulonglong2 v0 = r0[c];
                aRe = ffma2(hv.x, v0.x, aRe); aRo = ffma2(hv.y, v0.y, aRo);
                ulonglong2 v1 = r1[c];
                aZe = ffma2(hv.x, v1.x, aZe); aZo = ffma2(hv.y, v1.y, aZo);
                ulonglong2 v2 = r2[c];
                aNhe = ffma2(hv.x, v2.x, aNhe); aNho = ffma2(hv.y, v2.y, aNho);
            }
        }
        // gi_x (K-half of 128)
        {
            const ulonglong2* xp = reinterpret_cast<const ulonglong2*>(x_s + b * XS + half * 64);
            const ulonglong2* r0 = reinterpret_cast<const ulonglong2*>(wiR + half * 64);
            const ulonglong2* r1 = reinterpret_cast<const ulonglong2*>(wiZ + half * 64);
            const ulonglong2* r2 = reinterpret_cast<const ulonglong2*>(wiN + half * 64);
            #pragma unroll 8
            for (int c = 0; c < 16; c++) {
                ulonglong2 xv = xp[c];
                ulonglong2 v0 = r0[c];
                aRe = ffma2(xv.x, v0.x, aRe); aRo = ffma2(xv.y, v0.y, aRo);
                ulonglong2 v1 = r1[c];
                aZe = ffma2(xv.x, v1.x, aZe); aZo = ffma2(xv.y, v1.y, aZo);
                ulonglong2 v2 = r2[c];
                aNie = ffma2(xv.x, v2.x, aNie); aNio = ffma2(xv.y, v2.y, aNio);
            }
        }

        // wait for all y pieces, stage y (8 rows x 64 floats = 128 float4)
        if (t > 0) {
            if (tid < NSLICE) { while ((int)ld_acq(&g_yflag[fbase + tid]) < t) { } }
            __syncthreads();                               // S3
            if (tid < 128) {
                int row = tid >> 4, c = tid & 15;
                float4 v = reinterpret_cast<const float4*>(g_y[cur])[(b0 + row) * 16 + c];
                *reinterpret_cast<float4*>(y_s + row * YS + c * 4) = v;
            }
            __syncthreads();                               // S4
        }

        // gi_y (K-half of 64)
        {
            const ulonglong2* yp = reinterpret_cast<const ulonglong2*>(y_s + b * YS + half * 32);
            const ulonglong2* r0 = reinterpret_cast<const ulonglong2*>(wiR + INSZ + half * 32);
            const ulonglong2* r1 = reinterpret_cast<const ulonglong2*>(wiZ + INSZ + half * 32);
            const ulonglong2* r2 = reinterpret_cast<const ulonglong2*>(wiN + INSZ + half * 32);
            #pragma unroll
            for (int c = 0; c < 8; c++) {
                ulonglong2 yv = yp[c];
                ulonglong2 v0 = r0[c];
                aRe = ffma2(yv.x, v0.x, aRe); aRo = ffma2(yv.y, v0.y, aRo);
                ulonglong2 v1 = r1[c];
                aZe = ffma2(yv.x, v1.x, aZe); aZo = ffma2(yv.y, v1.y, aZo);
                ulonglong2 v2 = r2[c];
                aNie = ffma2(yv.x, v2.x, aNie); aNio = ffma2(yv.y, v2.y, aNio);
            }
        }

        float pR  = sumf2(aRe)  + sumf2(aRo);
        float pZ  = sumf2(aZe)  + sumf2(aZo);
        float pNi = sumf2(aNie) + sumf2(aNio);
        float pNh = sumf2(aNhe) + sumf2(aNho);

        if (half == 1) p_s[(warp & 7) * 32 + lane] = make_float4(pR, pZ, pNi, pNh);
        __syncthreads();                                   // S5

        if (half == 0) {
            float4 pp = p_s[warp * 32 + lane];
            float preR = pR + pp.x + bih_s[unit]      + bhh_s[unit];
            float preZ = pZ + pp.y + bih_s[32 + unit] + bhh_s[32 + unit];
            float giN  = pNi + pp.z + bih_s[64 + unit];
            float ghN  = pNh + pp.w + bhh_s[64 + unit];
            float r = 1.0f / (1.0f + __expf(-preR));
            float z = 1.0f / (1.0f + __expf(-preZ));
            float n = tanhf(giN + r * ghN);
            float hprev = h_s[b * HS + slice * UNITS + unit];
            float hnew = (1.0f - z) * n + z * hprev;
            hstg_s[b * HSTG + unit] = hnew;
            barn(2, 256);
            // coalesced writeback: 64 threads store 8 rows x 32 floats
            if (tid < 64) {
                int row = tid >> 3, cg = tid & 7;
                float4 v = *reinterpret_cast<float4*>(hstg_s + row * HSTG + cg * 4);
                reinterpret_cast<float4*>(g_h[nxt])
                    [(b0 + row) * 64 + (slice * UNITS >> 2) + cg] = v;
                __threadfence();
                barn(1, 64);
                if (tid == 0) st_rel(&g_hflag[blk], (unsigned)(t + 1));
            }
        }
    }

    // final: y_T = tanh(fc(h_T)) from g_h[0]
    if (tid < NSLICE) { while ((int)ld_acq(&g_hflag[fbase + tid]) < TSTEPS) { } }
    __syncthreads();
    {
        int row = tid >> 6, c = tid & 63;
        float4 v = reinterpret_cast<const float4*>(g_h[0])[(b0 + row) * 64 + c];
        *reinterpret_cast<float4*>(h_s + row * HS + c * 4) = v;
    }
    __syncthreads();
    if (tid < 64) {
        const int yb = tid & 7, ol = tid >> 3;
        const ulonglong2* hp = reinterpret_cast<const ulonglong2*>(h_s + yb * HS);
        const ulonglong2* fp = reinterpret_cast<const ulonglong2*>(fc_s + ol * FCS);
        ull a0 = 0, a1 = 0;
        #pragma unroll 8
        for (int c = 0; c < 64; c++) {
            ulonglong2 hv = hp[c], fv = fp[c];
            a0 = ffma2(hv.x, fv.x, a0);
            a1 = ffma2(hv.y, fv.y, a1);
        }
        out[(b0 + yb) * OUTSZ + slice * 8 + ol] =
            tanhf(sumf2(a0) + sumf2(a1) + fcb_s[ol]);
    }
}

extern "C" void kernel_launch(void* const* d_in, const int* in_sizes, int n_in,
                              void* d_out, int out_size) {
    (void)in_sizes; (void)n_in; (void)out_size;
    const float* x    = (const float*)d_in[0];
    const float* w_ih = (const float*)d_in[1];
    const float* w_hh = (const float*)d_in[2];
    const float* b_ih = (const float*)d_in[3];
    const float* b_hh = (const float*)d_in[4];
    const float* fc_w = (const float*)d_in[5];
    const float* fc_b = (const float*)d_in[6];
    float* out = (float*)d_out;

    const int smem_floats = ROWS * HS + ROWS * XS + ROWS * YS + 256 * 4 +
                            ROWS * HSTG + 96 * WHS + 96 * WIS + 8 * FCS +
                            96 + 96 + 8 + 8;
    const int smem_bytes = smem_floats * (int)sizeof(float); // ~209 KB

    cudaFuncSetAttribute(jordan_kernel,
                         cudaFuncAttributeMaxDynamicSharedMemorySize,
                         smem_bytes);

    jordan_init_kernel<<<64, 256>>>();
    jordan_kernel<<<NBLK, NTHR, smem_bytes>>>(x, w_ih, w_hh, b_ih, b_hh,
                                              fc_w, fc_b, out);
}